// round 1
// baseline (speedup 1.0000x reference)
#include <cuda_runtime.h>
#include <cstdint>

#define N_SAMP 4096
#define Fh 15
#define Wd 120
#define NWIN 12
#define Sw 10
#define Pn 105
#define HPR 270
#define K1 43200
#define N1 512
#define N2 128

// Scratch (device globals -- no allocation anywhere)
__device__ float g_act[(size_t)N_SAMP * K1];   // 708 MB conv activations
__device__ float g_y1[(size_t)N_SAMP * N1];    // 8 MB fc1 output

// fill(): replace inf/nan with 0 (bit test, robust under fast-math)
__device__ __forceinline__ float ffill(float x) {
    unsigned u = __float_as_uint(x);
    return ((u & 0x7f800000u) == 0x7f800000u) ? 0.0f : x;
}

// ---- packed f32x2 helpers (sm_100+ PTX) ----
__device__ __forceinline__ unsigned long long pk2(float lo, float hi) {
    unsigned long long r;
    asm("mov.b64 %0, {%1, %2};" : "=l"(r) : "f"(lo), "f"(hi));
    return r;
}
__device__ __forceinline__ void fma2(unsigned long long& d, unsigned long long a,
                                     unsigned long long b) {
    asm("fma.rn.f32x2 %0, %1, %2, %0;" : "+l"(d) : "l"(a), "l"(b));
}
__device__ __forceinline__ void upk2(unsigned long long v, float& lo, float& hi) {
    asm("mov.b64 {%0, %1}, %2;" : "=f"(lo), "=f"(hi) : "l"(v));
}

// ============================================================================
// Kernel 1: features + BN + Conv(1,16,(1,3)) + ReLU -> g_act [N][16*270*10]
// One block per sample.
// ============================================================================
__global__ __launch_bounds__(256) void feat_kernel(
    const float* __restrict__ data,
    const float* __restrict__ bn_gamma, const float* __restrict__ bn_beta,
    const float* __restrict__ bn_mean, const float* __restrict__ bn_var,
    const float* __restrict__ conv_w, const float* __restrict__ conv_b)
{
    __shared__ float sd[Fh * Wd];        // raw data, then overwritten by spread
    __shared__ float sstd[Fh * NWIN];
    __shared__ float sfeat[HPR * NWIN];  // BN-applied feature map [270][12]
    __shared__ float scw[48];
    __shared__ float scb[16];

    const int tid = threadIdx.x;
    const int n = blockIdx.x;
    const float* dptr = data + (size_t)n * (Fh * Wd);
    for (int i = tid; i < Fh * Wd; i += 256) sd[i] = dptr[i];
    if (tid < 48) scw[tid] = conv_w[tid];
    if (tid >= 64 && tid < 80) scb[tid - 64] = conv_b[tid - 64];
    const float bscale = rsqrtf(bn_var[0] + 1e-5f) * bn_gamma[0];
    const float bshift = bn_beta[0] - bn_mean[0] * bscale;
    __syncthreads();

    // Per (f, window): mean/std/zscore/return/decaylinear; overwrite sd with spread
    if (tid < Fh * NWIN) {
        const int f = tid / NWIN, w = tid % NWIN;
        float* seg = &sd[f * Wd + w * Sw];
        float mean = 0.f;
        #pragma unroll
        for (int s = 0; s < Sw; s++) mean += seg[s];
        mean *= 0.1f;
        float ret = ffill(seg[Sw - 1] / seg[0] - 1.0f);
        float dl = 0.f;
        #pragma unroll
        for (int s = 0; s < Sw; s++) dl += seg[s] * (float)(s + 1);
        dl *= (1.0f / 55.0f);
        float ss = 0.f;
        #pragma unroll
        for (int s = 0; s < Sw; s++) { float sp = seg[s] - mean; seg[s] = sp; ss += sp * sp; }
        const float sdv = sqrtf(ss * (1.0f / 9.0f));
        sstd[tid] = sdv;
        sfeat[(210 + f) * NWIN + w] = ffill(sdv) * bscale + bshift;
        sfeat[(225 + f) * NWIN + w] = ffill(mean / sdv) * bscale + bshift;
        sfeat[(240 + f) * NWIN + w] = ret * bscale + bshift;
        sfeat[(255 + f) * NWIN + w] = ffill(dl) * bscale + bshift;
    }
    __syncthreads();

    // Pairwise cov / corr (105 pairs x 12 windows)
    for (int idx = tid; idx < Pn * NWIN; idx += 256) {
        const int p = idx / NWIN, w = idx % NWIN;
        int i = 0, rem = p;
        while (rem >= 14 - i) { rem -= 14 - i; i++; }
        const int j = i + 1 + rem;
        const float* si = &sd[i * Wd + w * Sw];
        const float* sj = &sd[j * Wd + w * Sw];
        float dot = 0.f;
        #pragma unroll
        for (int s = 0; s < Sw; s++) dot += si[s] * sj[s];
        const float cov = dot * (1.0f / 9.0f);
        const float corr = ffill(cov / (sstd[i * NWIN + w] * sstd[j * NWIN + w]) * 0.9f);
        sfeat[p * NWIN + w]         = corr * bscale + bshift;
        sfeat[(105 + p) * NWIN + w] = ffill(cov) * bscale + bshift;
    }
    __syncthreads();

    // Conv(1->16, (1,3)) valid + ReLU, write flattened [o*2700 + h*10 + wc]
    float* aout = g_act + (size_t)n * K1;
    for (int idx = tid; idx < K1; idx += 256) {
        const int o = idx / 2700;
        const int rem = idx - o * 2700;
        const int h = rem / 10;
        const int wc = rem - h * 10;
        const float* fr = &sfeat[h * NWIN + wc];
        float v = scb[o] + scw[o * 3] * fr[0] + scw[o * 3 + 1] * fr[1] + scw[o * 3 + 2] * fr[2];
        aout[idx] = fmaxf(v, 0.0f);
    }
}

// ============================================================================
// Kernel 2: fc1 GEMM  Y[4096,512] = relu(A[4096,43200] @ W[512,43200]^T + b)
// 128x128 tile, BK=16, 256 threads, 8x8 microtile, packed f32x2 FMA,
// double-buffered smem.
// ============================================================================
__global__ __launch_bounds__(256) void fc1_gemm(
    const float* __restrict__ Wt, const float* __restrict__ bias)
{
    __shared__ float As[2][16][128];
    __shared__ float Bs[2][16][128];

    const int tid = threadIdx.x;
    const int bx = blockIdx.x;  // N tile: 0..3
    const int by = blockIdx.y;  // M tile: 0..31
    const float* Ab = g_act + (size_t)(by * 128) * K1;
    const float* Wb = Wt + (size_t)(bx * 128) * K1;
    const int tm = tid >> 4;    // 0..15
    const int tn = tid & 15;    // 0..15

    float4 pa[2], pb[2];

    unsigned long long acc[8][4];
    #pragma unroll
    for (int i = 0; i < 8; i++)
        #pragma unroll
        for (int j = 0; j < 4; j++) acc[i][j] = 0ULL;

    // prologue load tile 0
    {
        #pragma unroll
        for (int q = 0; q < 2; q++) {
            int v = tid + (q << 8);
            int row = v >> 2, kq = (v & 3) << 2;
            pa[q] = *(const float4*)(Ab + (size_t)row * K1 + kq);
            pb[q] = *(const float4*)(Wb + (size_t)row * K1 + kq);
        }
        #pragma unroll
        for (int q = 0; q < 2; q++) {
            int v = tid + (q << 8);
            int row = v >> 2, kq = (v & 3) << 2;
            As[0][kq + 0][row] = pa[q].x; As[0][kq + 1][row] = pa[q].y;
            As[0][kq + 2][row] = pa[q].z; As[0][kq + 3][row] = pa[q].w;
            Bs[0][kq + 0][row] = pb[q].x; Bs[0][kq + 1][row] = pb[q].y;
            Bs[0][kq + 2][row] = pb[q].z; Bs[0][kq + 3][row] = pb[q].w;
        }
    }
    __syncthreads();

    const int NT = K1 / 16;  // 2700
    for (int kt = 0; kt < NT; kt++) {
        const int cur = kt & 1;
        if (kt + 1 < NT) {
            const int k0 = (kt + 1) << 4;
            #pragma unroll
            for (int q = 0; q < 2; q++) {
                int v = tid + (q << 8);
                int row = v >> 2, kq = (v & 3) << 2;
                pa[q] = *(const float4*)(Ab + (size_t)row * K1 + k0 + kq);
                pb[q] = *(const float4*)(Wb + (size_t)row * K1 + k0 + kq);
            }
        }
        #pragma unroll
        for (int k = 0; k < 16; k++) {
            float ra[8];
            *(float4*)&ra[0] = *(const float4*)&As[cur][k][tm * 4];
            *(float4*)&ra[4] = *(const float4*)&As[cur][k][64 + tm * 4];
            unsigned long long rb[4];
            *(ulonglong2*)&rb[0] = *(const ulonglong2*)&Bs[cur][k][tn * 4];
            *(ulonglong2*)&rb[2] = *(const ulonglong2*)&Bs[cur][k][64 + tn * 4];
            #pragma unroll
            for (int i = 0; i < 8; i++) {
                unsigned long long rap = pk2(ra[i], ra[i]);
                #pragma unroll
                for (int j = 0; j < 4; j++) fma2(acc[i][j], rap, rb[j]);
            }
        }
        if (kt + 1 < NT) {
            const int nxt = (kt + 1) & 1;
            #pragma unroll
            for (int q = 0; q < 2; q++) {
                int v = tid + (q << 8);
                int row = v >> 2, kq = (v & 3) << 2;
                As[nxt][kq + 0][row] = pa[q].x; As[nxt][kq + 1][row] = pa[q].y;
                As[nxt][kq + 2][row] = pa[q].z; As[nxt][kq + 3][row] = pa[q].w;
                Bs[nxt][kq + 0][row] = pb[q].x; Bs[nxt][kq + 1][row] = pb[q].y;
                Bs[nxt][kq + 2][row] = pb[q].z; Bs[nxt][kq + 3][row] = pb[q].w;
            }
        }
        __syncthreads();
    }

    // epilogue: bias + relu
    const int gcol0 = bx * 128 + tn * 4;
    #pragma unroll
    for (int i = 0; i < 8; i++) {
        const int grow = by * 128 + ((i < 4) ? (tm * 4 + i) : (64 + tm * 4 + (i - 4)));
        float* yr = g_y1 + (size_t)grow * N1;
        #pragma unroll
        for (int half = 0; half < 2; half++) {
            const int c0 = gcol0 + half * 64;
            float v0, v1, v2, v3;
            upk2(acc[i][half * 2 + 0], v0, v1);
            upk2(acc[i][half * 2 + 1], v2, v3);
            float4 o;
            o.x = fmaxf(v0 + bias[c0 + 0], 0.f);
            o.y = fmaxf(v1 + bias[c0 + 1], 0.f);
            o.z = fmaxf(v2 + bias[c0 + 2], 0.f);
            o.w = fmaxf(v3 + bias[c0 + 3], 0.f);
            *(float4*)(yr + c0) = o;
        }
    }
}

// ============================================================================
// Kernel 3: fused fc2(sigmoid) + fc3. One block = 32 rows, all 128 fc2 cols.
// ============================================================================
__global__ __launch_bounds__(256) void fc23_kernel(
    const float* __restrict__ w2, const float* __restrict__ b2,
    const float* __restrict__ w3, const float* __restrict__ b3,
    float* __restrict__ out)
{
    __shared__ float As[32][32];    // [k][m]
    __shared__ float Bs[32][128];   // [k][n]
    __shared__ float sbuf[32][128]; // sigmoid outputs
    __shared__ float sw3[128];

    const int tid = threadIdx.x;
    const int mb = blockIdx.x;  // 0..127
    const float* Ab = g_y1 + (size_t)(mb * 32) * N1;
    if (tid < 128) sw3[tid] = w3[tid];
    const int tm = tid >> 5;  // 0..7
    const int tn = tid & 31;  // 0..31

    float acc[4][4] = {};
    for (int kt = 0; kt < 16; kt++) {
        const int k0 = kt * 32;
        {
            const int row = tid >> 3, kq = (tid & 7) << 2;
            float4 a = *(const float4*)(Ab + (size_t)row * N1 + k0 + kq);
            As[kq + 0][row] = a.x; As[kq + 1][row] = a.y;
            As[kq + 2][row] = a.z; As[kq + 3][row] = a.w;
        }
        #pragma unroll
        for (int q = 0; q < 4; q++) {
            const int v = tid + q * 256;
            const int row = v >> 3, kq = (v & 7) << 2;
            float4 b = *(const float4*)(w2 + (size_t)row * N1 + k0 + kq);
            Bs[kq + 0][row] = b.x; Bs[kq + 1][row] = b.y;
            Bs[kq + 2][row] = b.z; Bs[kq + 3][row] = b.w;
        }
        __syncthreads();
        #pragma unroll
        for (int k = 0; k < 32; k++) {
            float ra[4], rb[4];
            *(float4*)ra = *(const float4*)&As[k][tm * 4];
            *(float4*)rb = *(const float4*)&Bs[k][tn * 4];
            #pragma unroll
            for (int i = 0; i < 4; i++)
                #pragma unroll
                for (int j = 0; j < 4; j++) acc[i][j] += ra[i] * rb[j];
        }
        __syncthreads();
    }

    #pragma unroll
    for (int i = 0; i < 4; i++)
        #pragma unroll
        for (int j = 0; j < 4; j++) {
            const float v = acc[i][j] + b2[tn * 4 + j];
            sbuf[tm * 4 + i][tn * 4 + j] = 1.0f / (1.0f + expf(-v));
        }
    __syncthreads();

    // fc3: warp tm reduces its 4 rows over 128 cols
    #pragma unroll
    for (int r = 0; r < 4; r++) {
        const int row = tm * 4 + r;
        float s = sbuf[row][tn] * sw3[tn] + sbuf[row][tn + 32] * sw3[tn + 32]
                + sbuf[row][tn + 64] * sw3[tn + 64] + sbuf[row][tn + 96] * sw3[tn + 96];
        #pragma unroll
        for (int o = 16; o; o >>= 1) s += __shfl_down_sync(0xffffffffu, s, o);
        if (tn == 0) out[mb * 32 + row] = s + b3[0];
    }
}

// ============================================================================
extern "C" void kernel_launch(void* const* d_in, const int* in_sizes, int n_in,
                              void* d_out, int out_size) {
    const float* data   = (const float*)d_in[0];
    const float* gamma  = (const float*)d_in[1];
    const float* beta   = (const float*)d_in[2];
    const float* mean   = (const float*)d_in[3];
    const float* var    = (const float*)d_in[4];
    const float* conv_w = (const float*)d_in[5];
    const float* conv_b = (const float*)d_in[6];
    const float* fc1_w  = (const float*)d_in[7];
    const float* fc1_b  = (const float*)d_in[8];
    const float* fc2_w  = (const float*)d_in[9];
    const float* fc2_b  = (const float*)d_in[10];
    const float* fc3_w  = (const float*)d_in[11];
    const float* fc3_b  = (const float*)d_in[12];
    float* out = (float*)d_out;

    feat_kernel<<<N_SAMP, 256>>>(data, gamma, beta, mean, var, conv_w, conv_b);
    dim3 g1(4, 32);
    fc1_gemm<<<g1, 256>>>(fc1_w, fc1_b);
    fc23_kernel<<<128, 256>>>(fc2_w, fc2_b, fc3_w, fc3_b, out);
}

// round 3
// speedup vs baseline: 3.1433x; 3.1433x over previous
#include <cuda_runtime.h>
#include <cuda_bf16.h>
#include <cstdint>

#define N_SAMP 4096
#define Fh 15
#define Wd 120
#define NWIN 12
#define Sw 10
#define Pn 105
#define HPR 270
#define K1 43200
#define N1 512
#define BK 64
#define NT (K1 / BK)   // 675
#define STAGES 3

// ---------------- device-global scratch (no allocations anywhere) ----------
__device__ __nv_bfloat16 g_Ahi[(size_t)N_SAMP * K1];  // 354 MB
__device__ __nv_bfloat16 g_Alo[(size_t)N_SAMP * K1];  // 354 MB
__device__ __nv_bfloat16 g_Whi[(size_t)N1 * K1];      // 44 MB
__device__ __nv_bfloat16 g_Wlo[(size_t)N1 * K1];      // 44 MB
__device__ float g_y1[(size_t)N_SAMP * N1];           // 8 MB

// ---------------- helpers ---------------------------------------------------
__device__ __forceinline__ float ffill(float x) {
    unsigned u = __float_as_uint(x);
    return ((u & 0x7f800000u) == 0x7f800000u) ? 0.0f : x;
}
__device__ __forceinline__ uint32_t smem_u32(const void* p) {
    uint32_t a;
    asm("{ .reg .u64 t; cvta.to.shared.u64 t, %1; cvt.u32.u64 %0, t; }" : "=r"(a) : "l"(p));
    return a;
}
#define SWZ(o) ((o) ^ (((o) >> 3) & 0x70))

__device__ __forceinline__ void ldsm4(uint32_t* r, uint32_t addr) {
    asm volatile("ldmatrix.sync.aligned.m8n8.x4.shared.b16 {%0,%1,%2,%3}, [%4];"
                 : "=r"(r[0]), "=r"(r[1]), "=r"(r[2]), "=r"(r[3]) : "r"(addr));
}
__device__ __forceinline__ void hmma(float* d, const uint32_t* a, const uint32_t* b) {
    asm volatile(
        "mma.sync.aligned.m16n8k16.row.col.f32.bf16.bf16.f32 "
        "{%0,%1,%2,%3},{%4,%5,%6,%7},{%8,%9},{%0,%1,%2,%3};"
        : "+f"(d[0]), "+f"(d[1]), "+f"(d[2]), "+f"(d[3])
        : "r"(a[0]), "r"(a[1]), "r"(a[2]), "r"(a[3]), "r"(b[0]), "r"(b[1]));
}

// ============================================================================
// Kernel 1: features + BN + Conv + ReLU -> bf16 hi/lo planes
// ============================================================================
__global__ __launch_bounds__(256) void feat_kernel(
    const float* __restrict__ data,
    const float* __restrict__ bn_gamma, const float* __restrict__ bn_beta,
    const float* __restrict__ bn_mean, const float* __restrict__ bn_var,
    const float* __restrict__ conv_w, const float* __restrict__ conv_b)
{
    __shared__ float sd[Fh * Wd];
    __shared__ float sstd[Fh * NWIN];
    __shared__ float sfeat[HPR * NWIN];
    __shared__ float scw[48];
    __shared__ float scb[16];

    const int tid = threadIdx.x;
    const int n = blockIdx.x;
    const float* dptr = data + (size_t)n * (Fh * Wd);
    for (int i = tid; i < Fh * Wd; i += 256) sd[i] = dptr[i];
    if (tid < 48) scw[tid] = conv_w[tid];
    if (tid >= 64 && tid < 80) scb[tid - 64] = conv_b[tid - 64];
    const float bscale = rsqrtf(bn_var[0] + 1e-5f) * bn_gamma[0];
    const float bshift = bn_beta[0] - bn_mean[0] * bscale;
    __syncthreads();

    if (tid < Fh * NWIN) {
        const int f = tid / NWIN, w = tid % NWIN;
        float* seg = &sd[f * Wd + w * Sw];
        float mean = 0.f;
        #pragma unroll
        for (int s = 0; s < Sw; s++) mean += seg[s];
        mean *= 0.1f;
        float ret = ffill(seg[Sw - 1] / seg[0] - 1.0f);
        float dl = 0.f;
        #pragma unroll
        for (int s = 0; s < Sw; s++) dl += seg[s] * (float)(s + 1);
        dl *= (1.0f / 55.0f);
        float ss = 0.f;
        #pragma unroll
        for (int s = 0; s < Sw; s++) { float sp = seg[s] - mean; seg[s] = sp; ss += sp * sp; }
        const float sdv = sqrtf(ss * (1.0f / 9.0f));
        sstd[tid] = sdv;
        sfeat[(210 + f) * NWIN + w] = ffill(sdv) * bscale + bshift;
        sfeat[(225 + f) * NWIN + w] = ffill(mean / sdv) * bscale + bshift;
        sfeat[(240 + f) * NWIN + w] = ret * bscale + bshift;
        sfeat[(255 + f) * NWIN + w] = ffill(dl) * bscale + bshift;
    }
    __syncthreads();

    for (int idx = tid; idx < Pn * NWIN; idx += 256) {
        const int p = idx / NWIN, w = idx % NWIN;
        int i = 0, rem = p;
        while (rem >= 14 - i) { rem -= 14 - i; i++; }
        const int j = i + 1 + rem;
        const float* si = &sd[i * Wd + w * Sw];
        const float* sj = &sd[j * Wd + w * Sw];
        float dot = 0.f;
        #pragma unroll
        for (int s = 0; s < Sw; s++) dot += si[s] * sj[s];
        const float cov = dot * (1.0f / 9.0f);
        const float corr = ffill(cov / (sstd[i * NWIN + w] * sstd[j * NWIN + w]) * 0.9f);
        sfeat[p * NWIN + w]         = corr * bscale + bshift;
        sfeat[(105 + p) * NWIN + w] = ffill(cov) * bscale + bshift;
    }
    __syncthreads();

    // Conv + ReLU, split fp32 -> bf16 hi + bf16 lo planes
    __nv_bfloat16* ah = g_Ahi + (size_t)n * K1;
    __nv_bfloat16* al = g_Alo + (size_t)n * K1;
    for (int idx = tid; idx < K1; idx += 256) {
        const int o = idx / 2700;
        const int rem = idx - o * 2700;
        const int h = rem / 10;
        const int wc = rem - h * 10;
        const float* fr = &sfeat[h * NWIN + wc];
        float v = scb[o] + scw[o * 3] * fr[0] + scw[o * 3 + 1] * fr[1] + scw[o * 3 + 2] * fr[2];
        v = fmaxf(v, 0.0f);
        __nv_bfloat16 hi = __float2bfloat16(v);
        __nv_bfloat16 lo = __float2bfloat16(v - __bfloat162float(hi));
        ah[idx] = hi;
        al[idx] = lo;
    }
}

// ============================================================================
// Kernel 1b: split fc1 weights into bf16 hi/lo planes
// ============================================================================
__global__ __launch_bounds__(256) void wconv_kernel(const float* __restrict__ w) {
    const size_t i = ((size_t)blockIdx.x * 256 + threadIdx.x) * 4;
    float4 v = *(const float4*)(w + i);
    ushort4 hs, ls;
    {
        __nv_bfloat16 h = __float2bfloat16(v.x);
        hs.x = __bfloat16_as_ushort(h);
        ls.x = __bfloat16_as_ushort(__float2bfloat16(v.x - __bfloat162float(h)));
    }
    {
        __nv_bfloat16 h = __float2bfloat16(v.y);
        hs.y = __bfloat16_as_ushort(h);
        ls.y = __bfloat16_as_ushort(__float2bfloat16(v.y - __bfloat162float(h)));
    }
    {
        __nv_bfloat16 h = __float2bfloat16(v.z);
        hs.z = __bfloat16_as_ushort(h);
        ls.z = __bfloat16_as_ushort(__float2bfloat16(v.z - __bfloat162float(h)));
    }
    {
        __nv_bfloat16 h = __float2bfloat16(v.w);
        hs.w = __bfloat16_as_ushort(h);
        ls.w = __bfloat16_as_ushort(__float2bfloat16(v.w - __bfloat162float(h)));
    }
    *(ushort4*)((unsigned short*)g_Whi + i) = hs;
    *(ushort4*)((unsigned short*)g_Wlo + i) = ls;
}

// ============================================================================
// Kernel 2: fc1 via mma.sync bf16 split GEMM (sm_103-baseline tensor path)
// Y = relu((Ahi+Alo)@(Whi+Wlo)^T + b), dropping lo*lo.
// CTA 128x128, warp grid 2x4 (warp tile 64x32), BK=64, 3-stage cp.async.
// smem per stage: 4 planes x [128 rows x 128B] (SW128 swizzle) = 64KB.
// ============================================================================
__global__ __launch_bounds__(256) void fc1_mma(const float* __restrict__ bias)
{
    extern __shared__ __align__(1024) char smem[];
    const int tid = threadIdx.x;
    const int bx = blockIdx.x;   // N tile 0..3
    const int by = blockIdx.y;   // M tile 0..31
    const int warp = tid >> 5, lane = tid & 31;
    const int wm = warp >> 2;    // 0..1
    const int wn = warp & 3;     // 0..3
    const uint32_t sbase = smem_u32(smem);

    const __nv_bfloat16* gp0 = g_Ahi + (size_t)(by * 128) * K1;
    const __nv_bfloat16* gp1 = g_Alo + (size_t)(by * 128) * K1;
    const __nv_bfloat16* gp2 = g_Whi + (size_t)(bx * 128) * K1;
    const __nv_bfloat16* gp3 = g_Wlo + (size_t)(bx * 128) * K1;

    // per-thread cp.async geometry: chunk (16B) ch fixed, 4 rows per plane
    const int ch = tid & 7;
    const int rbase = tid >> 3;  // 0..31

    auto issue_stage = [&](int kt, int slot) {
        const int k0 = kt * BK;
        const uint32_t sb = sbase + (uint32_t)slot * 65536u;
        #pragma unroll
        for (int p = 0; p < 16; p++) {
            const int plane = p >> 2;
            const int row = ((p & 3) << 5) + rbase;
            const __nv_bfloat16* g =
                (plane == 0 ? gp0 : plane == 1 ? gp1 : plane == 2 ? gp2 : gp3)
                + (size_t)row * K1 + k0 + ch * 8;
            const uint32_t sa = sb + (uint32_t)plane * 16384u
                              + SWZ((uint32_t)(row * 128 + ch * 16));
            asm volatile("cp.async.cg.shared.global [%0], [%1], 16;"
                         :: "r"(sa), "l"(g));
        }
        asm volatile("cp.async.commit_group;");
    };

    issue_stage(0, 0);
    issue_stage(1, 1);

    float acc[4][4][4];
    #pragma unroll
    for (int i = 0; i < 4; i++)
        #pragma unroll
        for (int j = 0; j < 4; j++)
            #pragma unroll
            for (int q = 0; q < 4; q++) acc[i][j][q] = 0.f;

    // ldmatrix per-lane address components
    const uint32_t a_row_off = (uint32_t)((wm * 64 + (lane & 15)) * 128);
    const uint32_t a_k_off   = (uint32_t)((lane >> 4) << 4);
    const uint32_t b_row_off = (uint32_t)((wn * 32 + ((lane >> 4) << 3) + (lane & 7)) * 128);
    const uint32_t b_k_off   = (uint32_t)(((lane >> 3) & 1) << 4);

    for (int kt = 0; kt < NT; kt++) {
        asm volatile("cp.async.wait_group 1;");
        __syncthreads();
        if (kt + 2 < NT) issue_stage(kt + 2, (kt + 2) % STAGES);
        else asm volatile("cp.async.commit_group;");

        const uint32_t sb = sbase + (uint32_t)(kt % STAGES) * 65536u;
        #pragma unroll
        for (int s = 0; s < 4; s++) {
            uint32_t ahi[4][4], alo[4][4];
            #pragma unroll
            for (int mt = 0; mt < 4; mt++) {
                const uint32_t off = a_row_off + mt * 2048 + s * 32 + a_k_off;
                ldsm4(ahi[mt], sb + SWZ(off));
                ldsm4(alo[mt], sb + 16384u + SWZ(off));
            }
            uint32_t bhi[2][4], blo[2][4];
            #pragma unroll
            for (int q = 0; q < 2; q++) {
                const uint32_t off = b_row_off + q * 2048 + s * 32 + b_k_off;
                ldsm4(bhi[q], sb + 32768u + SWZ(off));
                ldsm4(blo[q], sb + 49152u + SWZ(off));
            }
            #pragma unroll
            for (int mt = 0; mt < 4; mt++)
                #pragma unroll
                for (int nt = 0; nt < 4; nt++) {
                    const uint32_t* bh = &bhi[nt >> 1][(nt & 1) << 1];
                    const uint32_t* bl = &blo[nt >> 1][(nt & 1) << 1];
                    hmma(acc[mt][nt], ahi[mt], bh);
                    hmma(acc[mt][nt], ahi[mt], bl);
                    hmma(acc[mt][nt], alo[mt], bh);
                }
        }
    }

    // epilogue: bias + relu, float2 stores
    #pragma unroll
    for (int mt = 0; mt < 4; mt++) {
        const int r0 = by * 128 + wm * 64 + mt * 16 + (lane >> 2);
        #pragma unroll
        for (int nt = 0; nt < 4; nt++) {
            const int c = bx * 128 + wn * 32 + nt * 8 + ((lane & 3) << 1);
            const float b0 = __ldg(bias + c), b1 = __ldg(bias + c + 1);
            float2 v0, v1;
            v0.x = fmaxf(acc[mt][nt][0] + b0, 0.f);
            v0.y = fmaxf(acc[mt][nt][1] + b1, 0.f);
            v1.x = fmaxf(acc[mt][nt][2] + b0, 0.f);
            v1.y = fmaxf(acc[mt][nt][3] + b1, 0.f);
            *(float2*)(g_y1 + (size_t)r0 * N1 + c) = v0;
            *(float2*)(g_y1 + (size_t)(r0 + 8) * N1 + c) = v1;
        }
    }
}

// ============================================================================
// Kernel 3: fused fc2(sigmoid) + fc3
// ============================================================================
__global__ __launch_bounds__(256) void fc23_kernel(
    const float* __restrict__ w2, const float* __restrict__ b2,
    const float* __restrict__ w3, const float* __restrict__ b3,
    float* __restrict__ out)
{
    __shared__ float As[32][32];
    __shared__ float Bs[32][128];
    __shared__ float sbuf[32][128];
    __shared__ float sw3[128];

    const int tid = threadIdx.x;
    const int mb = blockIdx.x;
    const float* Ab = g_y1 + (size_t)(mb * 32) * N1;
    if (tid < 128) sw3[tid] = w3[tid];
    const int tm = tid >> 5;
    const int tn = tid & 31;

    float acc[4][4] = {};
    for (int kt = 0; kt < 16; kt++) {
        const int k0 = kt * 32;
        {
            const int row = tid >> 3, kq = (tid & 7) << 2;
            float4 a = *(const float4*)(Ab + (size_t)row * N1 + k0 + kq);
            As[kq + 0][row] = a.x; As[kq + 1][row] = a.y;
            As[kq + 2][row] = a.z; As[kq + 3][row] = a.w;
        }
        #pragma unroll
        for (int q = 0; q < 4; q++) {
            const int v = tid + q * 256;
            const int row = v >> 3, kq = (v & 7) << 2;
            float4 b = *(const float4*)(w2 + (size_t)row * N1 + k0 + kq);
            Bs[kq + 0][row] = b.x; Bs[kq + 1][row] = b.y;
            Bs[kq + 2][row] = b.z; Bs[kq + 3][row] = b.w;
        }
        __syncthreads();
        #pragma unroll
        for (int k = 0; k < 32; k++) {
            float ra[4], rb[4];
            *(float4*)ra = *(const float4*)&As[k][tm * 4];
            *(float4*)rb = *(const float4*)&Bs[k][tn * 4];
            #pragma unroll
            for (int i = 0; i < 4; i++)
                #pragma unroll
                for (int j = 0; j < 4; j++) acc[i][j] += ra[i] * rb[j];
        }
        __syncthreads();
    }

    #pragma unroll
    for (int i = 0; i < 4; i++)
        #pragma unroll
        for (int j = 0; j < 4; j++) {
            const float v = acc[i][j] + b2[tn * 4 + j];
            sbuf[tm * 4 + i][tn * 4 + j] = 1.0f / (1.0f + expf(-v));
        }
    __syncthreads();

    #pragma unroll
    for (int r = 0; r < 4; r++) {
        const int row = tm * 4 + r;
        float s = sbuf[row][tn] * sw3[tn] + sbuf[row][tn + 32] * sw3[tn + 32]
                + sbuf[row][tn + 64] * sw3[tn + 64] + sbuf[row][tn + 96] * sw3[tn + 96];
        #pragma unroll
        for (int o = 16; o; o >>= 1) s += __shfl_down_sync(0xffffffffu, s, o);
        if (tn == 0) out[mb * 32 + row] = s + b3[0];
    }
}

// ============================================================================
extern "C" void kernel_launch(void* const* d_in, const int* in_sizes, int n_in,
                              void* d_out, int out_size) {
    const float* data   = (const float*)d_in[0];
    const float* gamma  = (const float*)d_in[1];
    const float* beta   = (const float*)d_in[2];
    const float* mean   = (const float*)d_in[3];
    const float* var    = (const float*)d_in[4];
    const float* conv_w = (const float*)d_in[5];
    const float* conv_b = (const float*)d_in[6];
    const float* fc1_w  = (const float*)d_in[7];
    const float* fc1_b  = (const float*)d_in[8];
    const float* fc2_w  = (const float*)d_in[9];
    const float* fc2_b  = (const float*)d_in[10];
    const float* fc3_w  = (const float*)d_in[11];
    const float* fc3_b  = (const float*)d_in[12];
    float* out = (float*)d_out;

    const int smem_sz = STAGES * 4 * 16384;  // 196608
    cudaFuncSetAttribute(fc1_mma, cudaFuncAttributeMaxDynamicSharedMemorySize, smem_sz);

    feat_kernel<<<N_SAMP, 256>>>(data, gamma, beta, mean, var, conv_w, conv_b);
    wconv_kernel<<<(N1 * K1) / (256 * 4), 256>>>(fc1_w);
    dim3 g1(4, 32);
    fc1_mma<<<g1, 256, smem_sz>>>(fc1_b);
    fc23_kernel<<<128, 256>>>(fc2_w, fc2_b, fc3_w, fc3_b, out);
}